// round 16
// baseline (speedup 1.0000x reference)
#include <cuda_runtime.h>
#include <cuda_fp16.h>
#include <cstdint>

#define N_FEAT 32
#define MAX_NODES 524288
#define NODE_MASK (MAX_NODES - 1)
#define MAX_EDGES 4194304

// Scratch: x/h fp16 (32 MB, L2-resident gather source), agg fp16 (32 MB x2),
// W fp16 (8 KB), rel-binned (src,dst) pairs (+pad).
__device__ __half g_xh[(size_t)MAX_NODES * N_FEAT];
__device__ __half g_agg1[(size_t)MAX_NODES * N_FEAT];
__device__ __half g_agg2[(size_t)MAX_NODES * N_FEAT];
__device__ __half g_wh[4 * 32 * 32];
__device__ uint4  g_esd4[(MAX_EDGES + 1024) / 2];     // viewed as uint2[]
__device__ int g_cnt4[4];
__device__ int g_off[5];    // padded bin starts (128-aligned), off[4] = padded total
__device__ int g_end[4];    // unpadded bin ends
__device__ int g_cursor[4];
__device__ unsigned int g_done;

// ---------------------------------------------------------------------------
// prep: x fp32 -> fp16, W fp32 -> fp16, zero agg1, reset counters.
// grid = nnodes*4/256 blocks; thread handles 8 floats -> 8 halfs + 1 uint4 zero.
// ---------------------------------------------------------------------------
__global__ void __launch_bounds__(256) prep_k(
    const float* __restrict__ x, const float* __restrict__ W,
    __half* __restrict__ xh, __half* __restrict__ agg1)
{
    const int gt = blockIdx.x * 256 + threadIdx.x;
    const float4* x4 = reinterpret_cast<const float4*>(x);
    const float4 v0 = __ldg(x4 + gt * 2);
    const float4 v1 = __ldg(x4 + gt * 2 + 1);
    __half2 h[4];
    h[0] = __floats2half2_rn(v0.x, v0.y);
    h[1] = __floats2half2_rn(v0.z, v0.w);
    h[2] = __floats2half2_rn(v1.x, v1.y);
    h[3] = __floats2half2_rn(v1.z, v1.w);
    reinterpret_cast<uint4*>(xh)[gt] = *reinterpret_cast<uint4*>(h);
    reinterpret_cast<uint4*>(agg1)[gt] = make_uint4(0u, 0u, 0u, 0u);

    if (gt < 1024) {   // W: 4096 floats = 1024 float4
        const float4 wv = __ldg(reinterpret_cast<const float4*>(W) + gt);
        __half2 wp[2];
        wp[0] = __floats2half2_rn(wv.x, wv.y);
        wp[1] = __floats2half2_rn(wv.z, wv.w);
        *reinterpret_cast<uint2*>(g_wh + gt * 4) = *reinterpret_cast<uint2*>(wp);
    }
    if (gt == 0) {
        g_cnt4[0] = g_cnt4[1] = g_cnt4[2] = g_cnt4[3] = 0;
        g_done = 0u;
    }
}

// ---------------------------------------------------------------------------
// Rel histogram (warp-aggregated); last block computes PADDED offsets
// (128-aligned bin starts), bin ends, and cursors.
// ---------------------------------------------------------------------------
__global__ void __launch_bounds__(256) hist_k(const int* __restrict__ et, int ne)
{
    __shared__ int h[4];
    if (threadIdx.x < 4) h[threadIdx.x] = 0;
    __syncthreads();

    const int e = blockIdx.x * 256 + threadIdx.x;
    if (e < ne) {
        const int r = __ldg(et + e);
        const unsigned int mask = __match_any_sync(__activemask(), r);
        const unsigned int lt   = (1u << (threadIdx.x & 31)) - 1u;
        if ((mask & lt) == 0u)
            atomicAdd(&h[r], __popc(mask));
    }
    __syncthreads();

    if (threadIdx.x < 4 && h[threadIdx.x])
        atomicAdd(&g_cnt4[threadIdx.x], h[threadIdx.x]);
    __threadfence();
    __syncthreads();

    if (threadIdx.x == 0) {
        const unsigned int t = atomicAdd(&g_done, 1u);
        if (t == gridDim.x - 1) {
            int o = 0;
            #pragma unroll
            for (int r = 0; r < 4; r++) {
                g_off[r] = o; g_cursor[r] = o;
                g_end[r] = o + g_cnt4[r];
                o = (o + g_cnt4[r] + 127) & ~127;
            }
            g_off[4] = o;
            g_done = 0u;
        }
    }
}

// ---------------------------------------------------------------------------
// Reorder into padded rel bins; warp-aggregated ranking.
// ---------------------------------------------------------------------------
__global__ void __launch_bounds__(256) reorder_k(
    const int* __restrict__ src, const int* __restrict__ dst,
    const int* __restrict__ et, int ne)
{
    __shared__ int h[4];
    __shared__ int base[4];
    if (threadIdx.x < 4) h[threadIdx.x] = 0;
    __syncthreads();

    uint2* esd = reinterpret_cast<uint2*>(g_esd4);
    const int e = blockIdx.x * 256 + threadIdx.x;
    int r = 0, pos_local = 0;
    uint2 sd = make_uint2(0u, 0u);
    const bool valid = (e < ne);
    if (valid) {
        r = __ldg(et + e);
        sd.x = (unsigned int)__ldg(src + e);
        sd.y = (unsigned int)__ldg(dst + e);
        const unsigned int mask = __match_any_sync(__activemask(), r);
        const unsigned int lt   = (1u << (threadIdx.x & 31)) - 1u;
        const int rank = __popc(mask & lt);
        int wbase = 0;
        if (rank == 0) wbase = atomicAdd(&h[r], __popc(mask));
        const int leader = __ffs(mask) - 1;
        wbase = __shfl_sync(0xffffffffu, wbase, leader);
        pos_local = wbase + rank;
    }
    __syncthreads();
    if (threadIdx.x < 4)
        base[threadIdx.x] = atomicAdd(&g_cursor[threadIdx.x], h[threadIdx.x]);
    __syncthreads();
    if (valid) esd[base[r] + pos_local] = sd;
}

// ---------------------------------------------------------------------------
// FUSED transform+scatter: block = 128 same-rel edges.
// Gather x rows (L2-resident 32 MB) -> smem, MMA against W_r (B-frags
// preloaded in regs), stage messages in smem, fp16 vector-RED to agg[dst].
// Pad/overrun edges: REDs skipped (e >= g_end[r]); stale src masked in-bounds.
// ---------------------------------------------------------------------------
__global__ void __launch_bounds__(256) fused_k(
    const __half* __restrict__ xh, __half* __restrict__ agg)
{
    __shared__ __align__(16) uint2  sds[128];        // 1 KB
    __shared__ __align__(16) __half xs[128 * 40];    // 10 KB
    __shared__ __align__(16) __half wh[32 * 40];     // 2.5 KB
    __shared__ __align__(16) __half cs[8][16 * 40];  // 10 KB

    const int tid  = threadIdx.x;
    const int base = blockIdx.x * 128;
    const int r = (base >= __ldg(&g_off[1])) + (base >= __ldg(&g_off[2]))
                + (base >= __ldg(&g_off[3]));
    const int eend = __ldg(&g_end[r]);

    // Load W_r (2 KB) into smem rows [d][o] with pad-40 stride.
    if (tid < 128) {
        const uint4 wv = __ldg(reinterpret_cast<const uint4*>(g_wh + r * 1024) + tid);
        const int d = tid >> 2, o4 = tid & 3;
        *reinterpret_cast<uint4*>(&wh[d * 40 + o4 * 8]) = wv;
    }
    // Load 128 (src,dst) pairs.
    if (tid < 64) {
        const uint4 ev = __ldg(g_esd4 + (base >> 1) + tid);
        sds[tid * 2]     = make_uint2(ev.x, ev.y);
        sds[tid * 2 + 1] = make_uint2(ev.z, ev.w);
    }
    __syncthreads();

    // Gather 128 x rows (64 B each) -> xs. 512 uint4 tasks.
    #pragma unroll
    for (int t = tid; t < 512; t += 256) {
        const int i = t >> 2, c = t & 3;
        const unsigned int s = sds[i].x & NODE_MASK;
        const uint4 v = __ldg(reinterpret_cast<const uint4*>(xh + ((size_t)s << 5)) + c);
        *reinterpret_cast<uint4*>(&xs[i * 40 + c * 8]) = v;
    }
    __syncthreads();

    const int w    = tid >> 5;
    const int lane = tid & 31;
    const int m0   = w * 16;

    // B fragments (4 n-tiles x 2 k-steps), loop-invariant.
    uint32_t bf[4][2][2];
    #pragma unroll
    for (int j = 0; j < 4; j++)
        #pragma unroll
        for (int s = 0; s < 2; s++) {
            const int krow = s * 16 + (lane & 15);
            const uint32_t ba =
                (uint32_t)__cvta_generic_to_shared(&wh[krow * 40 + j * 8]);
            asm volatile("ldmatrix.sync.aligned.m8n8.x2.trans.shared.b16 {%0,%1}, [%2];"
                         : "=r"(bf[j][s][0]), "=r"(bf[j][s][1]) : "r"(ba));
        }

    // A fragments: this warp's 16 edges.
    uint32_t a[2][4];
    #pragma unroll
    for (int s = 0; s < 2; s++) {
        const int row = m0 + (lane & 15);
        const int col = s * 16 + ((lane >> 4) << 3);
        const uint32_t aa =
            (uint32_t)__cvta_generic_to_shared(&xs[row * 40 + col]);
        asm volatile("ldmatrix.sync.aligned.m8n8.x4.shared.b16 {%0,%1,%2,%3}, [%4];"
                     : "=r"(a[s][0]), "=r"(a[s][1]), "=r"(a[s][2]), "=r"(a[s][3])
                     : "r"(aa));
    }

    // MMA + stage messages (fp16) into this warp's private cs slice.
    const int g  = lane >> 2;
    const int t4 = lane & 3;
    #pragma unroll
    for (int j = 0; j < 4; j++) {
        float acc[4] = {0.f, 0.f, 0.f, 0.f};
        #pragma unroll
        for (int s = 0; s < 2; s++) {
            asm volatile(
                "mma.sync.aligned.m16n8k16.row.col.f32.f16.f16.f32 "
                "{%0,%1,%2,%3}, {%4,%5,%6,%7}, {%8,%9}, {%0,%1,%2,%3};"
                : "+f"(acc[0]), "+f"(acc[1]), "+f"(acc[2]), "+f"(acc[3])
                : "r"(a[s][0]), "r"(a[s][1]), "r"(a[s][2]), "r"(a[s][3]),
                  "r"(bf[j][s][0]), "r"(bf[j][s][1]));
        }
        *reinterpret_cast<__half2*>(&cs[w][g * 40 + j * 8 + t4 * 2]) =
            __floats2half2_rn(acc[0], acc[1]);
        *reinterpret_cast<__half2*>(&cs[w][(g + 8) * 40 + j * 8 + t4 * 2]) =
            __floats2half2_rn(acc[2], acc[3]);
    }
    __syncwarp();

    // RED messages: 16 edges x 4 chunks = 64 tasks per warp.
    #pragma unroll
    for (int t = lane; t < 64; t += 32) {
        const int i = t >> 2, q = t & 3;
        if (base + m0 + i < eend) {
            const unsigned int d = sds[m0 + i].y;
            const uint4 v = *reinterpret_cast<const uint4*>(&cs[w][i * 40 + q * 8]);
            __half* ap = agg + ((size_t)d << 5) + q * 8;
            asm volatile("red.global.add.noftz.v4.f16x2 [%0], {%1, %2, %3, %4};"
                         :: "l"(ap), "r"(v.x), "r"(v.y), "r"(v.z), "r"(v.w)
                         : "memory");
        }
    }
}

// ---------------------------------------------------------------------------
// Inter-layer: xh = relu(agg1 + b) fp16; zero agg2.
// ---------------------------------------------------------------------------
__global__ void __launch_bounds__(256) inter_k(
    const __half* __restrict__ agg1, const float* __restrict__ b,
    __half* __restrict__ xh, __half* __restrict__ agg2)
{
    const int gt = blockIdx.x * 256 + threadIdx.x;
    const int c  = gt & 3;                 // feature chunk (8 features)
    const uint4 av = reinterpret_cast<const uint4*>(agg1)[gt];
    const __half2* hp = reinterpret_cast<const __half2*>(&av);
    const float4 b0 = __ldg(reinterpret_cast<const float4*>(b + c * 8));
    const float4 b1 = __ldg(reinterpret_cast<const float4*>(b + c * 8 + 4));
    const float bb[8] = {b0.x, b0.y, b0.z, b0.w, b1.x, b1.y, b1.z, b1.w};
    __half2 h[4];
    #pragma unroll
    for (int j = 0; j < 4; j++) {
        float2 fv = __half22float2(hp[j]);
        fv.x = fmaxf(fv.x + bb[j * 2 + 0], 0.f);
        fv.y = fmaxf(fv.y + bb[j * 2 + 1], 0.f);
        h[j] = __floats2half2_rn(fv.x, fv.y);
    }
    reinterpret_cast<uint4*>(xh)[gt] = *reinterpret_cast<uint4*>(h);
    reinterpret_cast<uint4*>(agg2)[gt] = make_uint4(0u, 0u, 0u, 0u);
}

// ---------------------------------------------------------------------------
// Pool: out[g][c] = mean_{i<32} relu(agg2[g*32+i][c] + b[c]).
// ---------------------------------------------------------------------------
__global__ void __launch_bounds__(256) pool_k(
    const __half* __restrict__ agg, const float* __restrict__ b,
    float* __restrict__ out, int nnodes)
{
    const int t = blockIdx.x * blockDim.x + threadIdx.x;
    if (t >= nnodes) return;
    const int c = t & 31;
    const int g = t >> 5;
    const float bc = __ldg(b + c);
    const __half* p = agg + (size_t)g * 32 * N_FEAT + c;
    float s = 0.f;
    #pragma unroll
    for (int i = 0; i < 32; i++)
        s += fmaxf(__half2float(p[i * N_FEAT]) + bc, 0.f);
    out[t] = s * (1.0f / 32.0f);
}

// ---------------------------------------------------------------------------
// Launch order: 0 prep, 1 hist, 2 reorder, 3 fused1 (ncu slot 3),
// 4 inter, 5 fused2, 6 pool.
// ---------------------------------------------------------------------------
extern "C" void kernel_launch(void* const* d_in, const int* in_sizes, int n_in,
                              void* d_out, int out_size)
{
    const float* x   = (const float*)d_in[0];
    const int*   src = (const int*)  d_in[1];
    const int*   dst = (const int*)  d_in[2];
    const int*   et  = (const int*)  d_in[3];
    const float* W   = (const float*)d_in[4];
    const float* b   = (const float*)d_in[5];

    const int nnodes = in_sizes[0] / N_FEAT;
    const int nedges = in_sizes[1];

    __half *xh, *agg1, *agg2;
    cudaGetSymbolAddress((void**)&xh,   g_xh);
    cudaGetSymbolAddress((void**)&agg1, g_agg1);
    cudaGetSymbolAddress((void**)&agg2, g_agg2);

    const int pv_blocks = nnodes * 4 / 256;            // 8192
    const int eb_blocks = (nedges + 255) / 256;
    const int fu_blocks = (nedges + 511) / 128;        // covers padded bins

    prep_k<<<pv_blocks, 256>>>(x, W, xh, agg1);
    hist_k<<<eb_blocks, 256>>>(et, nedges);
    reorder_k<<<eb_blocks, 256>>>(src, dst, et, nedges);
    fused_k<<<fu_blocks, 256>>>(xh, agg1);
    inter_k<<<pv_blocks, 256>>>(agg1, b, xh, agg2);
    fused_k<<<fu_blocks, 256>>>(xh, agg2);
    pool_k<<<(nnodes + 255) / 256, 256>>>(agg2, b, (float*)d_out, nnodes);
    (void)n_in; (void)out_size;
}

// round 17
// speedup vs baseline: 1.0304x; 1.0304x over previous
#include <cuda_runtime.h>
#include <cuda_fp16.h>
#include <cstdint>

#define N_FEAT 32
#define MAX_NODES 524288
#define NODE_MASK (MAX_NODES - 1)
#define MAX_EDGES 4194304

// Scratch: x/h fp16 (32 MB, L2-resident gather source), agg fp16 (32 MB x2),
// W fp16 (8 KB), rel-binned (src,dst) pairs (+pad).
__device__ __half g_xh[(size_t)MAX_NODES * N_FEAT];
__device__ __half g_agg1[(size_t)MAX_NODES * N_FEAT];
__device__ __half g_agg2[(size_t)MAX_NODES * N_FEAT];
__device__ __half g_wh[4 * 32 * 32];
__device__ uint4  g_esd4[(MAX_EDGES + 1024) / 2];     // viewed as uint2[]
__device__ int g_cnt4[4];
__device__ int g_off[5];    // padded bin starts (128-aligned), off[4] = padded total
__device__ int g_end[4];    // unpadded bin ends
__device__ int g_cursor[4];
__device__ unsigned int g_done;

// ---------------------------------------------------------------------------
// prep: x fp32 -> fp16, W fp32 -> fp16, zero agg1, reset counters.
// ---------------------------------------------------------------------------
__global__ void __launch_bounds__(256) prep_k(
    const float* __restrict__ x, const float* __restrict__ W,
    __half* __restrict__ xh, __half* __restrict__ agg1)
{
    const int gt = blockIdx.x * 256 + threadIdx.x;
    const float4* x4 = reinterpret_cast<const float4*>(x);
    const float4 v0 = __ldg(x4 + gt * 2);
    const float4 v1 = __ldg(x4 + gt * 2 + 1);
    __half2 h[4];
    h[0] = __floats2half2_rn(v0.x, v0.y);
    h[1] = __floats2half2_rn(v0.z, v0.w);
    h[2] = __floats2half2_rn(v1.x, v1.y);
    h[3] = __floats2half2_rn(v1.z, v1.w);
    reinterpret_cast<uint4*>(xh)[gt] = *reinterpret_cast<uint4*>(h);
    reinterpret_cast<uint4*>(agg1)[gt] = make_uint4(0u, 0u, 0u, 0u);

    if (gt < 1024) {   // W: 4096 floats = 1024 float4
        const float4 wv = __ldg(reinterpret_cast<const float4*>(W) + gt);
        __half2 wp[2];
        wp[0] = __floats2half2_rn(wv.x, wv.y);
        wp[1] = __floats2half2_rn(wv.z, wv.w);
        *reinterpret_cast<uint2*>(g_wh + gt * 4) = *reinterpret_cast<uint2*>(wp);
    }
    if (gt == 0) {
        g_cnt4[0] = g_cnt4[1] = g_cnt4[2] = g_cnt4[3] = 0;
        g_done = 0u;
    }
}

// ---------------------------------------------------------------------------
// Rel histogram (warp-aggregated); last block computes PADDED offsets,
// bin ends, and cursors.
// ---------------------------------------------------------------------------
__global__ void __launch_bounds__(256) hist_k(const int* __restrict__ et, int ne)
{
    __shared__ int h[4];
    if (threadIdx.x < 4) h[threadIdx.x] = 0;
    __syncthreads();

    const int e = blockIdx.x * 256 + threadIdx.x;
    if (e < ne) {
        const int r = __ldg(et + e);
        const unsigned int mask = __match_any_sync(__activemask(), r);
        const unsigned int lt   = (1u << (threadIdx.x & 31)) - 1u;
        if ((mask & lt) == 0u)
            atomicAdd(&h[r], __popc(mask));
    }
    __syncthreads();

    if (threadIdx.x < 4 && h[threadIdx.x])
        atomicAdd(&g_cnt4[threadIdx.x], h[threadIdx.x]);
    __threadfence();
    __syncthreads();

    if (threadIdx.x == 0) {
        const unsigned int t = atomicAdd(&g_done, 1u);
        if (t == gridDim.x - 1) {
            int o = 0;
            #pragma unroll
            for (int r = 0; r < 4; r++) {
                g_off[r] = o; g_cursor[r] = o;
                g_end[r] = o + g_cnt4[r];
                o = (o + g_cnt4[r] + 127) & ~127;
            }
            g_off[4] = o;
            g_done = 0u;
        }
    }
}

// ---------------------------------------------------------------------------
// Reorder into padded rel bins; warp-aggregated ranking.
// ---------------------------------------------------------------------------
__global__ void __launch_bounds__(256) reorder_k(
    const int* __restrict__ src, const int* __restrict__ dst,
    const int* __restrict__ et, int ne)
{
    __shared__ int h[4];
    __shared__ int base[4];
    if (threadIdx.x < 4) h[threadIdx.x] = 0;
    __syncthreads();

    uint2* esd = reinterpret_cast<uint2*>(g_esd4);
    const int e = blockIdx.x * 256 + threadIdx.x;
    int r = 0, pos_local = 0;
    uint2 sd = make_uint2(0u, 0u);
    const bool valid = (e < ne);
    if (valid) {
        r = __ldg(et + e);
        sd.x = (unsigned int)__ldg(src + e);
        sd.y = (unsigned int)__ldg(dst + e);
        const unsigned int mask = __match_any_sync(__activemask(), r);
        const unsigned int lt   = (1u << (threadIdx.x & 31)) - 1u;
        const int rank = __popc(mask & lt);
        int wbase = 0;
        if (rank == 0) wbase = atomicAdd(&h[r], __popc(mask));
        const int leader = __ffs(mask) - 1;
        wbase = __shfl_sync(0xffffffffu, wbase, leader);
        pos_local = wbase + rank;
    }
    __syncthreads();
    if (threadIdx.x < 4)
        base[threadIdx.x] = atomicAdd(&g_cursor[threadIdx.x], h[threadIdx.x]);
    __syncthreads();
    if (valid) esd[base[r] + pos_local] = sd;
}

// ---------------------------------------------------------------------------
// FUSED transform+scatter: block = 128 same-rel edges.
// L1-op diet vs R16: cp.async gather (1 op vs LDG+STS) and stmatrix staging
// (2 ops/warp vs 256 STS.32). ~17 L1 ops/edge.
// ---------------------------------------------------------------------------
__global__ void __launch_bounds__(256) fused_k(
    const __half* __restrict__ xh, __half* __restrict__ agg)
{
    __shared__ __align__(16) uint2  sds[128];        // 1 KB
    __shared__ __align__(16) __half xs[128 * 40];    // 10 KB
    __shared__ __align__(16) __half wh[32 * 40];     // 2.5 KB
    __shared__ __align__(16) __half cs[8][16 * 40];  // 10 KB

    const int tid  = threadIdx.x;
    const int base = blockIdx.x * 128;
    const int r = (base >= __ldg(&g_off[1])) + (base >= __ldg(&g_off[2]))
                + (base >= __ldg(&g_off[3]));
    const int eend = __ldg(&g_end[r]);

    // Load W_r (2 KB) into smem rows [d][o] with pad-40 stride.
    if (tid < 128) {
        const uint4 wv = __ldg(reinterpret_cast<const uint4*>(g_wh + r * 1024) + tid);
        const int d = tid >> 2, o4 = tid & 3;
        *reinterpret_cast<uint4*>(&wh[d * 40 + o4 * 8]) = wv;
    }
    // Load 128 (src,dst) pairs.
    if (tid < 64) {
        const uint4 ev = __ldg(g_esd4 + (base >> 1) + tid);
        sds[tid * 2]     = make_uint2(ev.x, ev.y);
        sds[tid * 2 + 1] = make_uint2(ev.z, ev.w);
    }
    __syncthreads();

    // Gather 128 x rows (64 B each) -> xs via cp.async (512 x 16 B).
    #pragma unroll
    for (int t = tid; t < 512; t += 256) {
        const int i = t >> 2, c = t & 3;
        const unsigned int s = sds[i].x & NODE_MASK;
        const __half* gp = xh + ((size_t)s << 5) + c * 8;
        const uint32_t sa = (uint32_t)__cvta_generic_to_shared(&xs[i * 40 + c * 8]);
        asm volatile("cp.async.ca.shared.global [%0], [%1], 16;"
                     :: "r"(sa), "l"(gp));
    }
    asm volatile("cp.async.commit_group;");
    asm volatile("cp.async.wait_group 0;");
    __syncthreads();

    const int w    = tid >> 5;
    const int lane = tid & 31;
    const int m0   = w * 16;

    // B fragments (4 n-tiles x 2 k-steps), loop-invariant.
    uint32_t bf[4][2][2];
    #pragma unroll
    for (int j = 0; j < 4; j++)
        #pragma unroll
        for (int s = 0; s < 2; s++) {
            const int krow = s * 16 + (lane & 15);
            const uint32_t ba =
                (uint32_t)__cvta_generic_to_shared(&wh[krow * 40 + j * 8]);
            asm volatile("ldmatrix.sync.aligned.m8n8.x2.trans.shared.b16 {%0,%1}, [%2];"
                         : "=r"(bf[j][s][0]), "=r"(bf[j][s][1]) : "r"(ba));
        }

    // A fragments: this warp's 16 edges.
    uint32_t a[2][4];
    #pragma unroll
    for (int s = 0; s < 2; s++) {
        const int row = m0 + (lane & 15);
        const int col = s * 16 + ((lane >> 4) << 3);
        const uint32_t aa =
            (uint32_t)__cvta_generic_to_shared(&xs[row * 40 + col]);
        asm volatile("ldmatrix.sync.aligned.m8n8.x4.shared.b16 {%0,%1,%2,%3}, [%4];"
                     : "=r"(a[s][0]), "=r"(a[s][1]), "=r"(a[s][2]), "=r"(a[s][3])
                     : "r"(aa));
    }

    // MMA; pack fp16 message fragments (exact stmatrix source layout).
    uint32_t c_lo[4], c_hi[4];
    #pragma unroll
    for (int j = 0; j < 4; j++) {
        float acc[4] = {0.f, 0.f, 0.f, 0.f};
        #pragma unroll
        for (int s = 0; s < 2; s++) {
            asm volatile(
                "mma.sync.aligned.m16n8k16.row.col.f32.f16.f16.f32 "
                "{%0,%1,%2,%3}, {%4,%5,%6,%7}, {%8,%9}, {%0,%1,%2,%3};"
                : "+f"(acc[0]), "+f"(acc[1]), "+f"(acc[2]), "+f"(acc[3])
                : "r"(a[s][0]), "r"(a[s][1]), "r"(a[s][2]), "r"(a[s][3]),
                  "r"(bf[j][s][0]), "r"(bf[j][s][1]));
        }
        __half2 lo = __floats2half2_rn(acc[0], acc[1]);
        __half2 hi = __floats2half2_rn(acc[2], acc[3]);
        c_lo[j] = *reinterpret_cast<uint32_t*>(&lo);
        c_hi[j] = *reinterpret_cast<uint32_t*>(&hi);
    }

    // Stage via stmatrix: matrix k (lanes 8k..8k+7 give addrs) = j-chunk k.
    {
        const int lr = lane & 7, lj = lane >> 3;
        const uint32_t sa_lo =
            (uint32_t)__cvta_generic_to_shared(&cs[w][lr * 40 + lj * 8]);
        const uint32_t sa_hi =
            (uint32_t)__cvta_generic_to_shared(&cs[w][(lr + 8) * 40 + lj * 8]);
        asm volatile("stmatrix.sync.aligned.m8n8.x4.shared.b16 [%0], {%1,%2,%3,%4};"
                     :: "r"(sa_lo), "r"(c_lo[0]), "r"(c_lo[1]), "r"(c_lo[2]), "r"(c_lo[3])
                     : "memory");
        asm volatile("stmatrix.sync.aligned.m8n8.x4.shared.b16 [%0], {%1,%2,%3,%4};"
                     :: "r"(sa_hi), "r"(c_hi[0]), "r"(c_hi[1]), "r"(c_hi[2]), "r"(c_hi[3])
                     : "memory");
    }
    __syncwarp();

    // RED messages: 16 edges x 4 chunks = 64 tasks per warp.
    #pragma unroll
    for (int t = lane; t < 64; t += 32) {
        const int i = t >> 2, q = t & 3;
        if (base + m0 + i < eend) {
            const unsigned int d = sds[m0 + i].y;
            const uint4 v = *reinterpret_cast<const uint4*>(&cs[w][i * 40 + q * 8]);
            __half* ap = agg + ((size_t)d << 5) + q * 8;
            asm volatile("red.global.add.noftz.v4.f16x2 [%0], {%1, %2, %3, %4};"
                         :: "l"(ap), "r"(v.x), "r"(v.y), "r"(v.z), "r"(v.w)
                         : "memory");
        }
    }
}

// ---------------------------------------------------------------------------
// Inter-layer: xh = relu(agg1 + b) fp16; zero agg2.
// ---------------------------------------------------------------------------
__global__ void __launch_bounds__(256) inter_k(
    const __half* __restrict__ agg1, const float* __restrict__ b,
    __half* __restrict__ xh, __half* __restrict__ agg2)
{
    const int gt = blockIdx.x * 256 + threadIdx.x;
    const int c  = gt & 3;
    const uint4 av = reinterpret_cast<const uint4*>(agg1)[gt];
    const __half2* hp = reinterpret_cast<const __half2*>(&av);
    const float4 b0 = __ldg(reinterpret_cast<const float4*>(b + c * 8));
    const float4 b1 = __ldg(reinterpret_cast<const float4*>(b + c * 8 + 4));
    const float bb[8] = {b0.x, b0.y, b0.z, b0.w, b1.x, b1.y, b1.z, b1.w};
    __half2 h[4];
    #pragma unroll
    for (int j = 0; j < 4; j++) {
        float2 fv = __half22float2(hp[j]);
        fv.x = fmaxf(fv.x + bb[j * 2 + 0], 0.f);
        fv.y = fmaxf(fv.y + bb[j * 2 + 1], 0.f);
        h[j] = __floats2half2_rn(fv.x, fv.y);
    }
    reinterpret_cast<uint4*>(xh)[gt] = *reinterpret_cast<uint4*>(h);
    reinterpret_cast<uint4*>(agg2)[gt] = make_uint4(0u, 0u, 0u, 0u);
}

// ---------------------------------------------------------------------------
// Pool: out[g][c] = mean_{i<32} relu(agg2[g*32+i][c] + b[c]).
// ---------------------------------------------------------------------------
__global__ void __launch_bounds__(256) pool_k(
    const __half* __restrict__ agg, const float* __restrict__ b,
    float* __restrict__ out, int nnodes)
{
    const int t = blockIdx.x * blockDim.x + threadIdx.x;
    if (t >= nnodes) return;
    const int c = t & 31;
    const int g = t >> 5;
    const float bc = __ldg(b + c);
    const __half* p = agg + (size_t)g * 32 * N_FEAT + c;
    float s = 0.f;
    #pragma unroll
    for (int i = 0; i < 32; i++)
        s += fmaxf(__half2float(p[i * N_FEAT]) + bc, 0.f);
    out[t] = s * (1.0f / 32.0f);
}

// ---------------------------------------------------------------------------
// Launch order: 0 prep, 1 hist, 2 reorder, 3 fused1 (ncu slot 3),
// 4 inter, 5 fused2, 6 pool.
// ---------------------------------------------------------------------------
extern "C" void kernel_launch(void* const* d_in, const int* in_sizes, int n_in,
                              void* d_out, int out_size)
{
    const float* x   = (const float*)d_in[0];
    const int*   src = (const int*)  d_in[1];
    const int*   dst = (const int*)  d_in[2];
    const int*   et  = (const int*)  d_in[3];
    const float* W   = (const float*)d_in[4];
    const float* b   = (const float*)d_in[5];

    const int nnodes = in_sizes[0] / N_FEAT;
    const int nedges = in_sizes[1];

    __half *xh, *agg1, *agg2;
    cudaGetSymbolAddress((void**)&xh,   g_xh);
    cudaGetSymbolAddress((void**)&agg1, g_agg1);
    cudaGetSymbolAddress((void**)&agg2, g_agg2);

    const int pv_blocks = nnodes * 4 / 256;            // 8192
    const int eb_blocks = (nedges + 255) / 256;
    const int fu_blocks = (nedges + 511) / 128;        // covers padded bins

    prep_k<<<pv_blocks, 256>>>(x, W, xh, agg1);
    hist_k<<<eb_blocks, 256>>>(et, nedges);
    reorder_k<<<eb_blocks, 256>>>(src, dst, et, nedges);
    fused_k<<<fu_blocks, 256>>>(xh, agg1);
    inter_k<<<pv_blocks, 256>>>(agg1, b, xh, agg2);
    fused_k<<<fu_blocks, 256>>>(xh, agg2);
    pool_k<<<(nnodes + 255) / 256, 256>>>(agg2, b, (float*)d_out, nnodes);
    (void)n_in; (void)out_size;
}